// round 13
// baseline (speedup 1.0000x reference)
#include <cuda_runtime.h>
#include <cuda_fp16.h>
#include <cstdint>

#define NN   50000
#define EE   1600000
#define HH   8
#define FF   16
#define INF  256
#define HF   128
#define SLOPE 0.2f

#define SB   128            // csr scan+scatter blocks (first in mega; <=148 resident)
#define NPB  392            // nodes per csr block (128*392 >= 50000)
#define MTILE 128
#define KC    64
#define LDT   72            // padded fp16 row stride (144B rows)
#define GB ((NN + MTILE - 1) / MTILE)   // 391 gemm blocks

#define HIB  384            // hist blocks in init
#define PBB  32             // prepB blocks in init

// dynamic smem layout (bytes)
#define SM_F32 0            // fp32 A staging: 128x64 f32 = 32768
#define SM_A0  32768        // fp16 A [128][72] = 18432
#define SM_A1  51200
#define SM_B0  69632
#define SM_B1  88064
#define SM_AL  106496
#define SM_AR  107008
#define SMEM_TOTAL 107520

// ---------------- scratch ----------------------------------------------------
__device__ __align__(16) __half g_Bh[HF * INF];     // W^T fp16 [n][k]
__device__ __align__(16) __half g_feath[NN * HF];   // 12.8 MB
__device__ __half g_elh[NN * HH];
__device__ __half g_erh[NN * HH];
__device__ float g_mbias[FF];
__device__ int   g_cnt[NN];          // zero at load; re-zeroed by agg each call
__device__ int   g_off[NN + 1];
__device__ int   g_cursor[NN];
__device__ int   g_csr_src[EE];
__device__ int   g_is64;
__device__ int   g_doneA;
__device__ int   g_doneB;
__device__ int   g_blocksum[SB];

// ---------------- ptx helpers -------------------------------------------------
__device__ __forceinline__ void mma16816(float* d, unsigned a0, unsigned a1,
                                         unsigned a2, unsigned a3,
                                         unsigned b0, unsigned b1) {
    asm volatile(
        "mma.sync.aligned.m16n8k16.row.col.f32.f16.f16.f32 "
        "{%0,%1,%2,%3}, {%4,%5,%6,%7}, {%8,%9}, {%0,%1,%2,%3};"
        : "+f"(d[0]), "+f"(d[1]), "+f"(d[2]), "+f"(d[3])
        : "r"(a0), "r"(a1), "r"(a2), "r"(a3), "r"(b0), "r"(b1));
}
__device__ __forceinline__ void cpa16(uint32_t s, const void* g) {
    asm volatile("cp.async.cg.shared.global [%0], [%1], 16;" :: "r"(s), "l"(g));
}
#define CP_COMMIT() asm volatile("cp.async.commit_group;" ::: "memory")
#define CP_WAIT0()  asm volatile("cp.async.wait_group 0;" ::: "memory")

// ---------------- block-local dtype detect ------------------------------------
__device__ __forceinline__ int detect_is64(const void* dstp, int tid) {
    __shared__ unsigned sany[8];
    unsigned v = ((const uint2*)dstp)[tid].y;
#pragma unroll
    for (int s = 16; s > 0; s >>= 1) v |= __shfl_xor_sync(0xffffffffu, v, s);
    if ((tid & 31) == 0) sany[tid >> 5] = v;
    __syncthreads();
    unsigned t = sany[0] | sany[1] | sany[2] | sany[3]
               | sany[4] | sany[5] | sany[6] | sany[7];
    return (t == 0u) ? 1 : 0;
}

// ---------------- init: hist (g_cnt pre-zeroed) | prepB -----------------------
__global__ __launch_bounds__(256) void init_kernel(const float* __restrict__ bias,
                                                   const void* __restrict__ dstp,
                                                   const float* __restrict__ W) {
    int b   = blockIdx.x;
    int tid = threadIdx.x;

    if (b < HIB) {
        int is64 = detect_is64(dstp, tid);
        if (b == 0 && tid == 0) {
            g_is64 = is64;
            g_doneA = 0;
            g_doneB = 0;
            g_off[NN] = EE;
        }
        if (b == 0 && tid < FF) {
            float s = 0.f;
#pragma unroll
            for (int h = 0; h < HH; h++) s += bias[h * FF + tid];
            g_mbias[tid] = 0.125f * s;
        }
        int stride = HIB * 256;
        for (int i = b * 256 + tid; i < EE / 2; i += stride) {
            int d0, d1;
            if (is64) {
                longlong2 v = ((const longlong2*)dstp)[i];
                d0 = (int)v.x; d1 = (int)v.y;
            } else {
                int2 v = ((const int2*)dstp)[i];
                d0 = v.x; d1 = v.y;
            }
            d0 = min(max(d0, 0), NN - 1);
            d1 = min(max(d1, 0), NN - 1);
            atomicAdd(&g_cnt[d0], 1);
            atomicAdd(&g_cnt[d1], 1);
        }
        return;
    }

    // prepB role: W -> transposed fp16 image [n][k]
    int gid = (b - HIB) * 256 + tid;
    int gs  = PBB * 256;
    for (int i = gid; i < HF * INF; i += gs) {
        int n = i >> 8, k = i & 255;
        g_Bh[i] = __float2half_rn(W[(size_t)k * HF + n]);
    }
}

// ---------------- mega kernel: scan+scatter | fp32->fp16 mma gemm -------------
__global__ __launch_bounds__(256)
void mega_kernel(const float* __restrict__ x,
                 const float* __restrict__ al,
                 const float* __restrict__ ar,
                 const void* __restrict__ srcp,
                 const void* __restrict__ dstp) {
    extern __shared__ char smem[];
    __shared__ int s_ws[8];
    __shared__ int s_red[256];

    int b   = blockIdx.x;
    int tid = threadIdx.x;

    // ======================= role 1: scan + scatter ===========================
    if (b < SB) {
        int sb = b;
        int i0 = sb * NPB + 2 * tid;
        int v0 = (2 * tid     < NPB && i0     < NN) ? __ldcg(&g_cnt[i0])     : 0;
        int v1 = (2 * tid + 1 < NPB && i0 + 1 < NN) ? __ldcg(&g_cnt[i0 + 1]) : 0;
        int v = v0 + v1;
        int lane = tid & 31, w = tid >> 5;
        int incl = v;
#pragma unroll
        for (int s = 1; s < 32; s <<= 1) {
            int t = __shfl_up_sync(0xffffffffu, incl, s);
            if (lane >= s) incl += t;
        }
        if (lane == 31) s_ws[w] = incl;
        __syncthreads();
        if (tid == 0) {
            int run = 0;
#pragma unroll
            for (int j = 0; j < 8; j++) { int t = s_ws[j]; s_ws[j] = run; run += t; }
        }
        __syncthreads();
        incl += s_ws[w];
        int lp = incl - v;

        if (tid == 255) g_blocksum[sb] = incl;
        __threadfence();
        __syncthreads();
        if (tid == 0) {
            atomicAdd(&g_doneA, 1);
            while (atomicAdd(&g_doneA, 0) < SB) __nanosleep(128);
        }
        __syncthreads();

        s_red[tid] = (tid < sb) ? __ldcg(&g_blocksum[tid]) : 0;
        __syncthreads();
        for (int s = 128; s > 0; s >>= 1) {
            if (tid < s) s_red[tid] += s_red[tid + s];
            __syncthreads();
        }
        int base = s_red[0];

        if (2 * tid < NPB && i0 < NN) {
            g_off[i0]    = base + lp;
            g_cursor[i0] = base + lp;
        }
        if (2 * tid + 1 < NPB && i0 + 1 < NN) {
            g_off[i0 + 1]    = base + lp + v0;
            g_cursor[i0 + 1] = base + lp + v0;
        }
        __threadfence();
        __syncthreads();
        if (tid == 0) {
            atomicAdd(&g_doneB, 1);
            while (atomicAdd(&g_doneB, 0) < SB) __nanosleep(128);
        }
        __syncthreads();

        // scatter (4 edges per iteration for ATOMG MLP)
        int is64 = g_is64;
        int stride = SB * 256;
        for (int e = sb * 256 + tid; e < EE / 4; e += stride) {
            int s0, s1, s2, s3, d0, d1, d2, d3;
            if (is64) {
                longlong2 sa = ((const longlong2*)srcp)[2 * e];
                longlong2 sbv = ((const longlong2*)srcp)[2 * e + 1];
                longlong2 da = ((const longlong2*)dstp)[2 * e];
                longlong2 db = ((const longlong2*)dstp)[2 * e + 1];
                s0 = (int)sa.x; s1 = (int)sa.y; s2 = (int)sbv.x; s3 = (int)sbv.y;
                d0 = (int)da.x; d1 = (int)da.y; d2 = (int)db.x; d3 = (int)db.y;
            } else {
                int4 sv = ((const int4*)srcp)[e];
                int4 dv = ((const int4*)dstp)[e];
                s0 = sv.x; s1 = sv.y; s2 = sv.z; s3 = sv.w;
                d0 = dv.x; d1 = dv.y; d2 = dv.z; d3 = dv.w;
            }
            s0 = min(max(s0, 0), NN - 1); s1 = min(max(s1, 0), NN - 1);
            s2 = min(max(s2, 0), NN - 1); s3 = min(max(s3, 0), NN - 1);
            d0 = min(max(d0, 0), NN - 1); d1 = min(max(d1, 0), NN - 1);
            d2 = min(max(d2, 0), NN - 1); d3 = min(max(d3, 0), NN - 1);
            int p0 = atomicAdd(&g_cursor[d0], 1);
            int p1 = atomicAdd(&g_cursor[d1], 1);
            int p2 = atomicAdd(&g_cursor[d2], 1);
            int p3 = atomicAdd(&g_cursor[d3], 1);
            g_csr_src[p0] = s0;
            g_csr_src[p1] = s1;
            g_csr_src[p2] = s2;
            g_csr_src[p3] = s3;
        }
        return;
    }

    // ======================= role 2: fp16 mma GEMM ============================
    int gb   = b - SB;
    int row0 = gb * MTILE;
    int wid  = tid >> 5;
    int lane = tid & 31;
    int wm   = wid >> 2;
    int wn   = wid & 3;
    uint32_t sbase = (uint32_t)__cvta_generic_to_shared(smem);
    float* sf32 = (float*)(smem + SM_F32);     // [128][64]
    float* salf = (float*)(smem + SM_AL);
    float* sarf = (float*)(smem + SM_AR);

    if (tid < HF) { salf[tid] = al[tid]; sarf[tid] = ar[tid]; }

    // zero fp32 staging if this block has OOB rows (stays zero: cp.async guarded)
    if (row0 + MTILE > NN) {
        for (int t = tid; t < 2048; t += 256)
            ((float4*)sf32)[t] = make_float4(0.f, 0.f, 0.f, 0.f);
    }
    __syncthreads();

    float acc[4][4][4];
#pragma unroll
    for (int mt = 0; mt < 4; mt++)
#pragma unroll
        for (int nt = 0; nt < 4; nt++)
#pragma unroll
            for (int q = 0; q < 4; q++) acc[mt][nt][q] = 0.f;

    // loaders
    auto loadA = [&](int c) {   // fp32 x chunk -> sf32 (256B/row = 16 segments)
        for (int t = tid; t < 2048; t += 256) {
            int r  = t >> 4;            // row
            int sg = t & 15;            // 16B segment (4 floats)
            int gr = row0 + r;
            if (gr < NN)
                cpa16(sbase + SM_F32 + r * 256 + sg * 16,
                      x + (size_t)gr * INF + c * KC + sg * 4);
        }
    };
    auto loadB = [&](int buf, int c) {
        uint32_t bbase = sbase + (buf ? SM_B1 : SM_B0);
        for (int t = tid; t < 1024; t += 256) {
            int n  = t >> 3;
            int sg = t & 7;
            cpa16(bbase + n * 144 + sg * 16,
                  g_Bh + (size_t)n * INF + c * KC + sg * 8);
        }
    };

    loadA(0); loadB(0, 0); CP_COMMIT();
    for (int c = 0; c < 4; c++) {
        CP_WAIT0();
        __syncthreads();
        // convert f32 staging -> fp16 tile [128][72]
        {
            __half* sAh = (__half*)(smem + ((c & 1) ? SM_A1 : SM_A0));
#pragma unroll
            for (int j = 0; j < 8; j++) {
                int t  = tid + j * 256;          // float4 index, 2048 total
                int r  = t >> 4;
                int cq = (t & 15) * 4;
                float4 v = ((const float4*)sf32)[t];
                __half2 h0 = __floats2half2_rn(v.x, v.y);
                __half2 h1 = __floats2half2_rn(v.z, v.w);
                *(uint2*)&sAh[r * LDT + cq] =
                    make_uint2(*(unsigned*)&h0, *(unsigned*)&h1);
            }
        }
        __syncthreads();
        if (c < 3) { loadA(c + 1); loadB((c + 1) & 1, c + 1); CP_COMMIT(); }

        __half* sA = (__half*)(smem + ((c & 1) ? SM_A1 : SM_A0));
        __half* sB = (__half*)(smem + ((c & 1) ? SM_B1 : SM_B0));
#pragma unroll
        for (int ks = 0; ks < 4; ks++) {
            int koff = ks * 16 + (lane & 3) * 2;
            unsigned bf[4][2];
#pragma unroll
            for (int nt = 0; nt < 4; nt++) {
                int n = (wn * 32 + nt * 8 + (lane >> 2)) * LDT + koff;
                bf[nt][0] = *(const unsigned*)&sB[n];
                bf[nt][1] = *(const unsigned*)&sB[n + 8];
            }
#pragma unroll
            for (int mt = 0; mt < 4; mt++) {
                int r = (wm * 64 + mt * 16 + (lane >> 2)) * LDT + koff;
                unsigned a0 = *(const unsigned*)&sA[r];
                unsigned a1 = *(const unsigned*)&sA[r + 8 * LDT];
                unsigned a2 = *(const unsigned*)&sA[r + 8];
                unsigned a3 = *(const unsigned*)&sA[r + 8 * LDT + 8];
#pragma unroll
                for (int nt = 0; nt < 4; nt++)
                    mma16816(acc[mt][nt], a0, a1, a2, a3, bf[nt][0], bf[nt][1]);
            }
        }
    }

    // epilogue: fp16 feat store + el/er from registers
#pragma unroll
    for (int mt = 0; mt < 4; mt++) {
        int rr0 = row0 + wm * 64 + mt * 16 + (lane >> 2);
        int rr1 = rr0 + 8;
        float el0[2] = {0.f, 0.f}, er0[2] = {0.f, 0.f};
        float el1[2] = {0.f, 0.f}, er1[2] = {0.f, 0.f};
#pragma unroll
        for (int nt = 0; nt < 4; nt++) {
            int col  = wn * 32 + nt * 8 + (lane & 3) * 2;
            int hsel = nt >> 1;
            float d0 = acc[mt][nt][0], d1 = acc[mt][nt][1];
            float d2 = acc[mt][nt][2], d3 = acc[mt][nt][3];
            el0[hsel] += d0 * salf[col] + d1 * salf[col + 1];
            er0[hsel] += d0 * sarf[col] + d1 * sarf[col + 1];
            el1[hsel] += d2 * salf[col] + d3 * salf[col + 1];
            er1[hsel] += d2 * sarf[col] + d3 * sarf[col + 1];
            if (rr0 < NN) {
                __half2 p = __floats2half2_rn(d0, d1);
                *(unsigned*)&g_feath[(size_t)rr0 * HF + col] = *(unsigned*)&p;
            }
            if (rr1 < NN) {
                __half2 p = __floats2half2_rn(d2, d3);
                *(unsigned*)&g_feath[(size_t)rr1 * HF + col] = *(unsigned*)&p;
            }
        }
#pragma unroll
        for (int s = 1; s <= 2; s <<= 1) {
            el0[0] += __shfl_xor_sync(0xffffffffu, el0[0], s);
            el0[1] += __shfl_xor_sync(0xffffffffu, el0[1], s);
            er0[0] += __shfl_xor_sync(0xffffffffu, er0[0], s);
            er0[1] += __shfl_xor_sync(0xffffffffu, er0[1], s);
            el1[0] += __shfl_xor_sync(0xffffffffu, el1[0], s);
            el1[1] += __shfl_xor_sync(0xffffffffu, el1[1], s);
            er1[0] += __shfl_xor_sync(0xffffffffu, er1[0], s);
            er1[1] += __shfl_xor_sync(0xffffffffu, er1[1], s);
        }
        if ((lane & 3) == 0) {
            if (rr0 < NN) {
                g_elh[rr0 * HH + 2 * wn]     = __float2half_rn(el0[0]);
                g_elh[rr0 * HH + 2 * wn + 1] = __float2half_rn(el0[1]);
                g_erh[rr0 * HH + 2 * wn]     = __float2half_rn(er0[0]);
                g_erh[rr0 * HH + 2 * wn + 1] = __float2half_rn(er0[1]);
            }
            if (rr1 < NN) {
                g_elh[rr1 * HH + 2 * wn]     = __float2half_rn(el1[0]);
                g_elh[rr1 * HH + 2 * wn + 1] = __float2half_rn(el1[1]);
                g_erh[rr1 * HH + 2 * wn]     = __float2half_rn(er1[0]);
                g_erh[rr1 * HH + 2 * wn + 1] = __float2half_rn(er1[1]);
            }
        }
    }
}

// ---------------- fused softmax-aggregate + classifier + cnt reset ------------
__global__ __launch_bounds__(256) void agg_kernel(float* __restrict__ out) {
    int gtid = blockIdx.x * blockDim.x + threadIdx.x;
    if (gtid < NN) g_cnt[gtid] = 0;   // re-zero for next invocation

    int n    = gtid >> 5;
    int lane = gtid & 31;
    if (n >= NN) return;
    int g   = lane >> 3;
    int sub = lane & 7;
    unsigned gm = 0xFFu << (g * 8);

    float ern = __half2float(g_erh[n * HH + sub]);
    int beg = g_off[n], end = g_off[n + 1];

    float accL[8], accH[8];
#pragma unroll
    for (int k = 0; k < 8; k++) { accL[k] = 0.f; accH[k] = 0.f; }
    float ssum = 0.f;

    int i  = beg + g;
    int sv = (i < end) ? g_csr_src[i] : -1;
    while (sv >= 0) {
        int ni  = i + 4;
        int nsv = (ni < end) ? g_csr_src[ni] : -1;
        const uint4* fp = (const uint4*)(g_feath + (size_t)sv * HF);
        uint4 f0 = fp[sub];
        uint4 f1 = fp[8 + sub];
        float e = __half2float(g_elh[sv * HH + sub]) + ern;
        e = fmaxf(e, 0.f) + SLOPE * fminf(e, 0.f);
        float exv = __expf(e);
        ssum += exv;
        float exL = __shfl_sync(gm, exv, (g << 3) + (sub >> 1));
        float exH = __shfl_sync(gm, exv, (g << 3) + 4 + (sub >> 1));
        float2 a0 = __half22float2(*reinterpret_cast<__half2*>(&f0.x));
        float2 a1 = __half22float2(*reinterpret_cast<__half2*>(&f0.y));
        float2 a2 = __half22float2(*reinterpret_cast<__half2*>(&f0.z));
        float2 a3 = __half22float2(*reinterpret_cast<__half2*>(&f0.w));
        float2 b0 = __half22float2(*reinterpret_cast<__half2*>(&f1.x));
        float2 b1 = __half22float2(*reinterpret_cast<__half2*>(&f1.y));
        float2 b2 = __half22float2(*reinterpret_cast<__half2*>(&f1.z));
        float2 b3 = __half22float2(*reinterpret_cast<__half2*>(&f1.w));
        accL[0] += exL * a0.x; accL[1] += exL * a0.y;
        accL[2] += exL * a1.x; accL[3] += exL * a1.y;
        accL[4] += exL * a2.x; accL[5] += exL * a2.y;
        accL[6] += exL * a3.x; accL[7] += exL * a3.y;
        accH[0] += exH * b0.x; accH[1] += exH * b0.y;
        accH[2] += exH * b1.x; accH[3] += exH * b1.y;
        accH[4] += exH * b2.x; accH[5] += exH * b2.y;
        accH[6] += exH * b3.x; accH[7] += exH * b3.y;
        i = ni; sv = nsv;
    }
    __syncwarp(0xffffffffu);

#pragma unroll
    for (int k = 0; k < 8; k++) {
        accL[k] += __shfl_xor_sync(0xffffffffu, accL[k], 8);
        accL[k] += __shfl_xor_sync(0xffffffffu, accL[k], 16);
        accH[k] += __shfl_xor_sync(0xffffffffu, accH[k], 8);
        accH[k] += __shfl_xor_sync(0xffffffffu, accH[k], 16);
    }
    ssum += __shfl_xor_sync(0xffffffffu, ssum, 8);
    ssum += __shfl_xor_sync(0xffffffffu, ssum, 16);

    float inv  = 1.f / fmaxf(ssum, 1e-9f);
    float invL = __shfl_sync(0xffffffffu, inv, (lane & 24) + (sub >> 1));
    float invH = __shfl_sync(0xffffffffu, inv, (lane & 24) + 4 + (sub >> 1));

    float v[8];
#pragma unroll
    for (int k = 0; k < 8; k++) v[k] = accL[k] * invL + accH[k] * invH;

#pragma unroll
    for (int k = 0; k < 8; k++) {
        v[k] += __shfl_xor_sync(0xffffffffu, v[k], 2);
        v[k] += __shfl_xor_sync(0xffffffffu, v[k], 4);
    }

    if (lane < 2) {
        float4 o0, o1;
        o0.x = v[0] * 0.125f + g_mbias[lane * 8 + 0];
        o0.y = v[1] * 0.125f + g_mbias[lane * 8 + 1];
        o0.z = v[2] * 0.125f + g_mbias[lane * 8 + 2];
        o0.w = v[3] * 0.125f + g_mbias[lane * 8 + 3];
        o1.x = v[4] * 0.125f + g_mbias[lane * 8 + 4];
        o1.y = v[5] * 0.125f + g_mbias[lane * 8 + 5];
        o1.z = v[6] * 0.125f + g_mbias[lane * 8 + 6];
        o1.w = v[7] * 0.125f + g_mbias[lane * 8 + 7];
        ((float4*)out)[n * 4 + lane * 2 + 0] = o0;
        ((float4*)out)[n * 4 + lane * 2 + 1] = o1;
    }
}

// ---------------- launch ------------------------------------------------------
extern "C" void kernel_launch(void* const* d_in, const int* in_sizes, int n_in,
                              void* d_out, int out_size) {
    const float* x    = (const float*)d_in[0];
    const float* W    = (const float*)d_in[1];
    const float* al   = (const float*)d_in[2];
    const float* ar   = (const float*)d_in[3];
    const float* bias = (const float*)d_in[4];
    const void*  src  = d_in[5];
    const void*  dst  = d_in[6];
    float* out = (float*)d_out;

    cudaFuncSetAttribute(mega_kernel, cudaFuncAttributeMaxDynamicSharedMemorySize,
                         SMEM_TOTAL);

    init_kernel<<<HIB + PBB, 256>>>(bias, dst, W);
    mega_kernel<<<SB + GB, 256, SMEM_TOTAL>>>(x, al, ar, src, dst);
    agg_kernel<<<(NN * 32 + 255) / 256, 256>>>(out);
}

// round 14
// speedup vs baseline: 1.1796x; 1.1796x over previous
#include <cuda_runtime.h>
#include <cuda_fp16.h>
#include <cstdint>

#define NN   50000
#define EE   1600000
#define HH   8
#define FF   16
#define INF  256
#define HF   128
#define SLOPE 0.2f

#define SB   256            // csr scan+scatter blocks (first in mega)
#define NPB  196            // nodes per csr block
#define MTILE 128
#define KC    64
#define LDT   72            // padded fp16 row stride (144B rows)
#define GB ((NN + MTILE - 1) / MTILE)   // 391 gemm blocks

#define HIB  512            // hist blocks inside init
#define CVB  512            // convert blocks inside init

// dynamic smem layout (bytes)
#define SM_A0 0
#define SM_B0 18432
#define SM_A1 36864
#define SM_B1 55296
#define SM_AL 73728
#define SM_AR 74240
#define SMEM_TOTAL 74752

// ---------------- scratch ----------------------------------------------------
__device__ __align__(16) __half g_xh[NN * INF];     // 25.6 MB fp16 x
__device__ __align__(16) __half g_Bh[HF * INF];     // W^T fp16 [n][k]
__device__ __align__(16) __half g_feath[NN * HF];   // 12.8 MB
__device__ __half g_elh[NN * HH];
__device__ __half g_erh[NN * HH];
__device__ float g_mbias[FF];
__device__ int   g_cnt[NN];          // zero at load; re-zeroed by agg each call
__device__ int   g_off[NN + 1];
__device__ int   g_cursor[NN];
__device__ int   g_csr_src[EE];
__device__ int   g_is64;
__device__ int   g_doneA;
__device__ int   g_doneB;
__device__ int   g_blocksum[SB];

// ---------------- ptx helpers -------------------------------------------------
__device__ __forceinline__ void mma16816(float* d, unsigned a0, unsigned a1,
                                         unsigned a2, unsigned a3,
                                         unsigned b0, unsigned b1) {
    asm volatile(
        "mma.sync.aligned.m16n8k16.row.col.f32.f16.f16.f32 "
        "{%0,%1,%2,%3}, {%4,%5,%6,%7}, {%8,%9}, {%0,%1,%2,%3};"
        : "+f"(d[0]), "+f"(d[1]), "+f"(d[2]), "+f"(d[3])
        : "r"(a0), "r"(a1), "r"(a2), "r"(a3), "r"(b0), "r"(b1));
}
__device__ __forceinline__ void cpa16(uint32_t s, const void* g) {
    asm volatile("cp.async.cg.shared.global [%0], [%1], 16;" :: "r"(s), "l"(g));
}
#define CP_COMMIT() asm volatile("cp.async.commit_group;" ::: "memory")
#define CP_WAIT1()  asm volatile("cp.async.wait_group 1;" ::: "memory")
#define CP_WAIT0()  asm volatile("cp.async.wait_group 0;" ::: "memory")

// ---------------- block-local dtype detect ------------------------------------
__device__ __forceinline__ int detect_is64(const void* dstp, int tid) {
    __shared__ unsigned sany[8];
    unsigned v = ((const uint2*)dstp)[tid].y;
#pragma unroll
    for (int s = 16; s > 0; s >>= 1) v |= __shfl_xor_sync(0xffffffffu, v, s);
    if ((tid & 31) == 0) sany[tid >> 5] = v;
    __syncthreads();
    unsigned t = sany[0] | sany[1] | sany[2] | sany[3]
               | sany[4] | sany[5] | sany[6] | sany[7];
    return (t == 0u) ? 1 : 0;
}

// ---------------- init: hist (g_cnt pre-zeroed) | convert x | prep ------------
__global__ __launch_bounds__(256) void init_kernel(const float* __restrict__ bias,
                                                   const void* __restrict__ dstp,
                                                   const float* __restrict__ x,
                                                   const float* __restrict__ W) {
    int b   = blockIdx.x;
    int tid = threadIdx.x;

    if (b < HIB) {
        // ---- histogram role (cnt zeroed by previous agg / module load) ----
        int is64 = detect_is64(dstp, tid);
        if (b == 0 && tid == 0) {
            g_is64 = is64;
            g_doneA = 0;
            g_doneB = 0;
            g_off[NN] = EE;
        }
        if (b == 0 && tid < FF) {
            float s = 0.f;
#pragma unroll
            for (int h = 0; h < HH; h++) s += bias[h * FF + tid];
            g_mbias[tid] = 0.125f * s;
        }
        int stride = HIB * 256;
        for (int i = b * 256 + tid; i < EE / 2; i += stride) {
            int d0, d1;
            if (is64) {
                longlong2 v = ((const longlong2*)dstp)[i];
                d0 = (int)v.x; d1 = (int)v.y;
            } else {
                int2 v = ((const int2*)dstp)[i];
                d0 = v.x; d1 = v.y;
            }
            d0 = min(max(d0, 0), NN - 1);
            d1 = min(max(d1, 0), NN - 1);
            atomicAdd(&g_cnt[d0], 1);
            atomicAdd(&g_cnt[d1], 1);
        }
        return;
    }

    // ---- convert role ----
    int gid = (b - HIB) * 256 + tid;
    int gs  = CVB * 256;
    for (int i = gid; i < NN * INF / 4; i += gs) {
        float4 v = ((const float4*)x)[i];
        __half2 h0 = __floats2half2_rn(v.x, v.y);
        __half2 h1 = __floats2half2_rn(v.z, v.w);
        *(uint2*)&g_xh[(size_t)i * 4] =
            make_uint2(*(unsigned*)&h0, *(unsigned*)&h1);
    }
    for (int i = gid; i < HF * INF; i += gs) {
        int n = i >> 8, k = i & 255;
        g_Bh[i] = __float2half_rn(W[(size_t)k * HF + n]);
    }
}

// ---------------- mega kernel: scan+scatter | fp16-mma gemm -------------------
__global__ __launch_bounds__(256, 2)
void mega_kernel(const float* __restrict__ al,
                 const float* __restrict__ ar,
                 const void* __restrict__ srcp,
                 const void* __restrict__ dstp) {
    extern __shared__ char smem[];
    __shared__ int s_ws[8];
    __shared__ int s_red[256];

    int b   = blockIdx.x;
    int tid = threadIdx.x;

    // ======================= role 1: scan + scatter ===========================
    if (b < SB) {
        int sb = b;
        int i = sb * NPB + tid;
        int v = (tid < NPB && i < NN) ? __ldcg(&g_cnt[i]) : 0;
        int lane = tid & 31, w = tid >> 5;
        int incl = v;
#pragma unroll
        for (int s = 1; s < 32; s <<= 1) {
            int t = __shfl_up_sync(0xffffffffu, incl, s);
            if (lane >= s) incl += t;
        }
        if (lane == 31) s_ws[w] = incl;
        __syncthreads();
        if (tid == 0) {
            int run = 0;
#pragma unroll
            for (int j = 0; j < 8; j++) { int t = s_ws[j]; s_ws[j] = run; run += t; }
        }
        __syncthreads();
        incl += s_ws[w];
        int lp = incl - v;

        if (tid == 255) g_blocksum[sb] = incl;
        __threadfence();
        __syncthreads();
        if (tid == 0) {
            atomicAdd(&g_doneA, 1);
            while (atomicAdd(&g_doneA, 0) < SB) __nanosleep(128);
        }
        __syncthreads();

        s_red[tid] = (tid < sb) ? __ldcg(&g_blocksum[tid]) : 0;
        __syncthreads();
        for (int s = 128; s > 0; s >>= 1) {
            if (tid < s) s_red[tid] += s_red[tid + s];
            __syncthreads();
        }
        int base = s_red[0];

        if (tid < NPB && i < NN) {
            g_off[i]    = base + lp;
            g_cursor[i] = base + lp;
        }
        __threadfence();
        __syncthreads();
        if (tid == 0) {
            atomicAdd(&g_doneB, 1);
            while (atomicAdd(&g_doneB, 0) < SB) __nanosleep(128);
        }
        __syncthreads();

        // scatter (4 edges per iteration for ATOMG MLP)
        int is64 = g_is64;
        int stride = SB * 256;
        for (int e = sb * 256 + tid; e < EE / 4; e += stride) {
            int s0, s1, s2, s3, d0, d1, d2, d3;
            if (is64) {
                longlong2 sa  = ((const longlong2*)srcp)[2 * e];
                longlong2 sbv = ((const longlong2*)srcp)[2 * e + 1];
                longlong2 da  = ((const longlong2*)dstp)[2 * e];
                longlong2 db  = ((const longlong2*)dstp)[2 * e + 1];
                s0 = (int)sa.x; s1 = (int)sa.y; s2 = (int)sbv.x; s3 = (int)sbv.y;
                d0 = (int)da.x; d1 = (int)da.y; d2 = (int)db.x; d3 = (int)db.y;
            } else {
                int4 sv = ((const int4*)srcp)[e];
                int4 dv = ((const int4*)dstp)[e];
                s0 = sv.x; s1 = sv.y; s2 = sv.z; s3 = sv.w;
                d0 = dv.x; d1 = dv.y; d2 = dv.z; d3 = dv.w;
            }
            s0 = min(max(s0, 0), NN - 1); s1 = min(max(s1, 0), NN - 1);
            s2 = min(max(s2, 0), NN - 1); s3 = min(max(s3, 0), NN - 1);
            d0 = min(max(d0, 0), NN - 1); d1 = min(max(d1, 0), NN - 1);
            d2 = min(max(d2, 0), NN - 1); d3 = min(max(d3, 0), NN - 1);
            int p0 = atomicAdd(&g_cursor[d0], 1);
            int p1 = atomicAdd(&g_cursor[d1], 1);
            int p2 = atomicAdd(&g_cursor[d2], 1);
            int p3 = atomicAdd(&g_cursor[d3], 1);
            g_csr_src[p0] = s0;
            g_csr_src[p1] = s1;
            g_csr_src[p2] = s2;
            g_csr_src[p3] = s3;
        }
        return;
    }

    // ======================= role 2: fp16 mma GEMM ============================
    int gb   = b - SB;
    int row0 = gb * MTILE;
    int wid  = tid >> 5;
    int lane = tid & 31;
    int wm   = wid >> 2;
    int wn   = wid & 3;
    uint32_t sbase = (uint32_t)__cvta_generic_to_shared(smem);
    float* salf = (float*)(smem + SM_AL);
    float* sarf = (float*)(smem + SM_AR);

    if (tid < HF) { salf[tid] = al[tid]; sarf[tid] = ar[tid]; }

    float acc[4][4][4];
#pragma unroll
    for (int mt = 0; mt < 4; mt++)
#pragma unroll
        for (int nt = 0; nt < 4; nt++)
#pragma unroll
            for (int q = 0; q < 4; q++) acc[mt][nt][q] = 0.f;

    auto load_chunk = [&](int buf, int c) {
        uint32_t abase = sbase + (buf ? SM_A1 : SM_A0);
        uint32_t bbase = sbase + (buf ? SM_B1 : SM_B0);
        for (int t = tid; t < 2048; t += 256) {
            int seg = t & 7;
            if (t < 1024) {
                int r  = t >> 3;
                int gr = row0 + r;
                if (gr < NN)
                    cpa16(abase + r * 144 + seg * 16,
                          g_xh + (size_t)gr * INF + c * KC + seg * 8);
            } else {
                int n = (t - 1024) >> 3;
                cpa16(bbase + n * 144 + seg * 16,
                      g_Bh + (size_t)n * INF + c * KC + seg * 8);
            }
        }
    };

    load_chunk(0, 0);
    CP_COMMIT();
    for (int c = 0; c < 4; c++) {
        if (c < 3) {
            load_chunk((c + 1) & 1, c + 1);
            CP_COMMIT();
            CP_WAIT1();
        } else {
            CP_WAIT0();
        }
        __syncthreads();
        __half* sA = (__half*)(smem + ((c & 1) ? SM_A1 : SM_A0));
        __half* sB = (__half*)(smem + ((c & 1) ? SM_B1 : SM_B0));
#pragma unroll
        for (int ks = 0; ks < 4; ks++) {
            int koff = ks * 16 + (lane & 3) * 2;
            unsigned bf[4][2];
#pragma unroll
            for (int nt = 0; nt < 4; nt++) {
                int n = (wn * 32 + nt * 8 + (lane >> 2)) * LDT + koff;
                bf[nt][0] = *(const unsigned*)&sB[n];
                bf[nt][1] = *(const unsigned*)&sB[n + 8];
            }
#pragma unroll
            for (int mt = 0; mt < 4; mt++) {
                int r = (wm * 64 + mt * 16 + (lane >> 2)) * LDT + koff;
                unsigned a0 = *(const unsigned*)&sA[r];
                unsigned a1 = *(const unsigned*)&sA[r + 8 * LDT];
                unsigned a2 = *(const unsigned*)&sA[r + 8];
                unsigned a3 = *(const unsigned*)&sA[r + 8 * LDT + 8];
#pragma unroll
                for (int nt = 0; nt < 4; nt++)
                    mma16816(acc[mt][nt], a0, a1, a2, a3, bf[nt][0], bf[nt][1]);
            }
        }
        __syncthreads();
    }

    // epilogue: fp16 feat store + el/er from registers
#pragma unroll
    for (int mt = 0; mt < 4; mt++) {
        int rr0 = row0 + wm * 64 + mt * 16 + (lane >> 2);
        int rr1 = rr0 + 8;
        float el0[2] = {0.f, 0.f}, er0[2] = {0.f, 0.f};
        float el1[2] = {0.f, 0.f}, er1[2] = {0.f, 0.f};
#pragma unroll
        for (int nt = 0; nt < 4; nt++) {
            int col  = wn * 32 + nt * 8 + (lane & 3) * 2;
            int hsel = nt >> 1;
            float d0 = acc[mt][nt][0], d1 = acc[mt][nt][1];
            float d2 = acc[mt][nt][2], d3 = acc[mt][nt][3];
            el0[hsel] += d0 * salf[col] + d1 * salf[col + 1];
            er0[hsel] += d0 * sarf[col] + d1 * sarf[col + 1];
            el1[hsel] += d2 * salf[col] + d3 * salf[col + 1];
            er1[hsel] += d2 * sarf[col] + d3 * sarf[col + 1];
            if (rr0 < NN) {
                __half2 p = __floats2half2_rn(d0, d1);
                *(unsigned*)&g_feath[(size_t)rr0 * HF + col] = *(unsigned*)&p;
            }
            if (rr1 < NN) {
                __half2 p = __floats2half2_rn(d2, d3);
                *(unsigned*)&g_feath[(size_t)rr1 * HF + col] = *(unsigned*)&p;
            }
        }
#pragma unroll
        for (int s = 1; s <= 2; s <<= 1) {
            el0[0] += __shfl_xor_sync(0xffffffffu, el0[0], s);
            el0[1] += __shfl_xor_sync(0xffffffffu, el0[1], s);
            er0[0] += __shfl_xor_sync(0xffffffffu, er0[0], s);
            er0[1] += __shfl_xor_sync(0xffffffffu, er0[1], s);
            el1[0] += __shfl_xor_sync(0xffffffffu, el1[0], s);
            el1[1] += __shfl_xor_sync(0xffffffffu, el1[1], s);
            er1[0] += __shfl_xor_sync(0xffffffffu, er1[0], s);
            er1[1] += __shfl_xor_sync(0xffffffffu, er1[1], s);
        }
        if ((lane & 3) == 0) {
            if (rr0 < NN) {
                g_elh[rr0 * HH + 2 * wn]     = __float2half_rn(el0[0]);
                g_elh[rr0 * HH + 2 * wn + 1] = __float2half_rn(el0[1]);
                g_erh[rr0 * HH + 2 * wn]     = __float2half_rn(er0[0]);
                g_erh[rr0 * HH + 2 * wn + 1] = __float2half_rn(er0[1]);
            }
            if (rr1 < NN) {
                g_elh[rr1 * HH + 2 * wn]     = __float2half_rn(el1[0]);
                g_elh[rr1 * HH + 2 * wn + 1] = __float2half_rn(el1[1]);
                g_erh[rr1 * HH + 2 * wn]     = __float2half_rn(er1[0]);
                g_erh[rr1 * HH + 2 * wn + 1] = __float2half_rn(er1[1]);
            }
        }
    }
}

// ---------------- fused softmax-aggregate + classifier + cnt reset ------------
__global__ __launch_bounds__(256) void agg_kernel(float* __restrict__ out) {
    int gtid = blockIdx.x * blockDim.x + threadIdx.x;
    if (gtid < NN) g_cnt[gtid] = 0;   // re-zero for next invocation

    int n    = gtid >> 5;
    int lane = gtid & 31;
    if (n >= NN) return;
    int g   = lane >> 3;
    int sub = lane & 7;
    unsigned gm = 0xFFu << (g * 8);

    float ern = __half2float(g_erh[n * HH + sub]);
    int beg = g_off[n], end = g_off[n + 1];

    float accL[8], accH[8];
#pragma unroll
    for (int k = 0; k < 8; k++) { accL[k] = 0.f; accH[k] = 0.f; }
    float ssum = 0.f;

    int i  = beg + g;
    int sv = (i < end) ? g_csr_src[i] : -1;
    while (sv >= 0) {
        int ni  = i + 4;
        int nsv = (ni < end) ? g_csr_src[ni] : -1;
        const uint4* fp = (const uint4*)(g_feath + (size_t)sv * HF);
        uint4 f0 = fp[sub];
        uint4 f1 = fp[8 + sub];
        float e = __half2float(g_elh[sv * HH + sub]) + ern;
        e = fmaxf(e, 0.f) + SLOPE * fminf(e, 0.f);
        float exv = __expf(e);
        ssum += exv;
        float exL = __shfl_sync(gm, exv, (g << 3) + (sub >> 1));
        float exH = __shfl_sync(gm, exv, (g << 3) + 4 + (sub >> 1));
        float2 a0 = __half22float2(*reinterpret_cast<__half2*>(&f0.x));
        float2 a1 = __half22float2(*reinterpret_cast<__half2*>(&f0.y));
        float2 a2 = __half22float2(*reinterpret_cast<__half2*>(&f0.z));
        float2 a3 = __half22float2(*reinterpret_cast<__half2*>(&f0.w));
        float2 b0 = __half22float2(*reinterpret_cast<__half2*>(&f1.x));
        float2 b1 = __half22float2(*reinterpret_cast<__half2*>(&f1.y));
        float2 b2 = __half22float2(*reinterpret_cast<__half2*>(&f1.z));
        float2 b3 = __half22float2(*reinterpret_cast<__half2*>(&f1.w));
        accL[0] += exL * a0.x; accL[1] += exL * a0.y;
        accL[2] += exL * a1.x; accL[3] += exL * a1.y;
        accL[4] += exL * a2.x; accL[5] += exL * a2.y;
        accL[6] += exL * a3.x; accL[7] += exL * a3.y;
        accH[0] += exH * b0.x; accH[1] += exH * b0.y;
        accH[2] += exH * b1.x; accH[3] += exH * b1.y;
        accH[4] += exH * b2.x; accH[5] += exH * b2.y;
        accH[6] += exH * b3.x; accH[7] += exH * b3.y;
        i = ni; sv = nsv;
    }
    __syncwarp(0xffffffffu);

#pragma unroll
    for (int k = 0; k < 8; k++) {
        accL[k] += __shfl_xor_sync(0xffffffffu, accL[k], 8);
        accL[k] += __shfl_xor_sync(0xffffffffu, accL[k], 16);
        accH[k] += __shfl_xor_sync(0xffffffffu, accH[k], 8);
        accH[k] += __shfl_xor_sync(0xffffffffu, accH[k], 16);
    }
    ssum += __shfl_xor_sync(0xffffffffu, ssum, 8);
    ssum += __shfl_xor_sync(0xffffffffu, ssum, 16);

    float inv  = 1.f / fmaxf(ssum, 1e-9f);
    float invL = __shfl_sync(0xffffffffu, inv, (lane & 24) + (sub >> 1));
    float invH = __shfl_sync(0xffffffffu, inv, (lane & 24) + 4 + (sub >> 1));

    float v[8];
#pragma unroll
    for (int k = 0; k < 8; k++) v[k] = accL[k] * invL + accH[k] * invH;

#pragma unroll
    for (int k = 0; k < 8; k++) {
        v[k] += __shfl_xor_sync(0xffffffffu, v[k], 2);
        v[k] += __shfl_xor_sync(0xffffffffu, v[k], 4);
    }

    if (lane < 2) {
        float4 o0, o1;
        o0.x = v[0] * 0.125f + g_mbias[lane * 8 + 0];
        o0.y = v[1] * 0.125f + g_mbias[lane * 8 + 1];
        o0.z = v[2] * 0.125f + g_mbias[lane * 8 + 2];
        o0.w = v[3] * 0.125f + g_mbias[lane * 8 + 3];
        o1.x = v[4] * 0.125f + g_mbias[lane * 8 + 4];
        o1.y = v[5] * 0.125f + g_mbias[lane * 8 + 5];
        o1.z = v[6] * 0.125f + g_mbias[lane * 8 + 6];
        o1.w = v[7] * 0.125f + g_mbias[lane * 8 + 7];
        ((float4*)out)[n * 4 + lane * 2 + 0] = o0;
        ((float4*)out)[n * 4 + lane * 2 + 1] = o1;
    }
}

// ---------------- launch ------------------------------------------------------
extern "C" void kernel_launch(void* const* d_in, const int* in_sizes, int n_in,
                              void* d_out, int out_size) {
    const float* x    = (const float*)d_in[0];
    const float* W    = (const float*)d_in[1];
    const float* al   = (const float*)d_in[2];
    const float* ar   = (const float*)d_in[3];
    const float* bias = (const float*)d_in[4];
    const void*  src  = d_in[5];
    const void*  dst  = d_in[6];
    float* out = (float*)d_out;

    cudaFuncSetAttribute(mega_kernel, cudaFuncAttributeMaxDynamicSharedMemorySize,
                         SMEM_TOTAL);

    init_kernel<<<HIB + CVB, 256>>>(bias, dst, x, W);
    mega_kernel<<<SB + GB, 256, SMEM_TOTAL>>>(al, ar, src, dst);
    agg_kernel<<<(NN * 32 + 255) / 256, 256>>>(out);
}